// round 8
// baseline (speedup 1.0000x reference)
#include <cuda_runtime.h>
#include <cstdint>

#define Wd 512
#define BATCH 16
#define NPIX (Wd * Wd)
#define NTOT (BATCH * NPIX)
#define PADW 520
#define PADH 516
#define PADN (PADW * PADH)
#define INV_CELL 2.56f  /* 1 / (200/512) */
#define ROWS_PB 8
#define FILL_BYTES ((ROWS_PB + 4) * PADW * 4)

// Padded tm1 (= terrain - 1) buffers, zero borders.
// Logical (i,j) lives at pad[(i+2)*PADW + (j+4)].
__device__ __align__(16) float g_padA[BATCH * PADN];
__device__ __align__(16) float g_padB[BATCH * PADN];
__device__ __align__(16) float g_sed[NTOT];
__device__ __align__(16) float g_wat[NTOT];
__device__ __align__(16) float g_vel[NTOT];
__device__ float g_par[8];

__global__ void param_kernel(const float* rr, const float* ev, const float* mh,
                             const float* he, const float* gr, const float* kc,
                             const float* di, const float* de) {
    g_par[0] = fmaxf(*rr, 0.0f);            // relu(rain_rate)
    g_par[1] = *he;                         // height_epsilon
    g_par[2] = *mh;                         // min_height_delta
    g_par[3] = fmaxf(*kc, 0.0f) * INV_CELL; // relu(kc)/CELL_W
    g_par[4] = *di;                         // dissolving_rate
    g_par[5] = *de;                         // deposition_rate
    g_par[6] = 1.0f - fmaxf(*ev, 0.0f);     // 1 - relu(evap)
    g_par[7] = fmaxf(*gr, 0.0f) * INV_CELL; // relu(g)/CELL_W
}

__global__ void init_kernel(const float* __restrict__ in) {
    int row = blockIdx.x;            // 0 .. BATCH*PADH-1
    int b = row / PADH;
    int pi = row - b * PADH;
    int pj = threadIdx.x;            // 0 .. 519
    int pidx = b * PADN + pi * PADW + pj;
    float v = 0.0f;
    if (pi >= 2 && pi < 2 + Wd && pj >= 4 && pj < 4 + Wd) {
        int i = pi - 2, j = pj - 4;
        int cidx = b * NPIX + i * Wd + j;
        float t0 = (1.0f - in[cidx]) * 0.5f;
        v = t0 - 1.0f;                       // reference's tm1, exactly
        g_sed[cidx] = 0.0f;
        g_wat[cidx] = 0.0f;
        g_vel[cidx] = 0.0f;
    }
    g_padA[pidx] = v;
    g_padB[pidx] = 0.0f;  // zero borders for B too; interior overwritten each step
}

__device__ __forceinline__ uint32_t smem_u32(const void* p) {
    uint32_t a;
    asm("{ .reg .u64 t; cvta.to.shared.u64 t, %1; cvt.u32.u64 %0, t; }"
        : "=r"(a) : "l"(p));
    return a;
}

template <bool LAST>
__global__ void __launch_bounds__(512)
step_kernel(const float* __restrict__ pin, float* __restrict__ pout,
            const float* __restrict__ rain, float* __restrict__ outp) {
    // padded rows i0..i0+11 (logical i0-2..i0+9)
    __shared__ __align__(16) float sm[(ROWS_PB + 4) * PADW];
    __shared__ __align__(8) unsigned long long mbar;

    int blk = blockIdx.x;
    int b = blk >> 6;            // batch (64 blocks per batch)
    int i0 = (blk & 63) << 3;    // first of 8 grid rows
    int t = threadIdx.x;
    int r = t >> 6;              // row within block (0..7)
    int q = t & 63;              // lane-position within row
    int i = i0 + r;

    uint32_t mb = smem_u32(&mbar);
    if (t == 0) {
        asm volatile("mbarrier.init.shared.b64 [%0], 1;" :: "r"(mb) : "memory");
    }
    __syncthreads();
    if (t == 0) {
        asm volatile("mbarrier.arrive.expect_tx.shared.b64 _, [%0], %1;"
                     :: "r"(mb), "r"(FILL_BYTES) : "memory");
        const float* src = pin + (size_t)b * PADN + (size_t)i0 * PADW;
        asm volatile(
            "cp.async.bulk.shared::cluster.global.mbarrier::complete_tx::bytes "
            "[%0], [%1], %2, [%3];"
            :: "r"(smem_u32(sm)), "l"(src), "r"(FILL_BYTES), "r"(mb) : "memory");
    }

    int cbase = b * NPIX + i * Wd;
    const float* rrow = rain + i * Wd;

    const float4* parv = reinterpret_cast<const float4*>(g_par);
    float4 pA = parv[0];  // x=rain_rate' y=heps z=minhd w=kc'
    float4 pB = parv[1];  // x=dis y=dep z=evap' w=grav'

    // ---- first half's state loads, front-batched to overlap the TMA fill ----
    float s_[4], w_[4], v_[4], rn_[4];
#pragma unroll
    for (int k = 0; k < 4; ++k) {
        int jj = q + (k << 6);
        s_[k]  = g_sed[cbase + jj];
        w_[k]  = g_wat[cbase + jj];
        v_[k]  = g_vel[cbase + jj];
        rn_[k] = rrow[jj];
    }

    // wait for TMA fill (phase 0) — HW-sleep try_wait, no issue-slot burn
    {
        uint32_t done;
        asm volatile(
            "{ .reg .pred p; mbarrier.try_wait.parity.shared.b64 p, [%1], 0, 0x989680; "
            "selp.u32 %0, 1, 0, p; }"
            : "=r"(done) : "r"(mb) : "memory");
        while (!done) {
            asm volatile(
                "{ .reg .pred p; mbarrier.try_wait.parity.shared.b64 p, [%1], 0, 0x989680; "
                "selp.u32 %0, 1, 0, p; }"
                : "=r"(done) : "r"(mb) : "memory");
        }
    }
    __syncthreads();

    const float* smc = sm + (r + 2) * PADW + 4;   // this row's center, logical col 0
    bool interior_i = (i > 0) && (i < Wd - 1);
    float rowsc = (i == 0) ? 1.1f : 0.9f;
    float fi = (float)i;
    float* porow = pout + (size_t)b * PADN + (size_t)(i + 2) * PADW + 4;

#pragma unroll
    for (int half = 0; half < 2; ++half) {
        if (half == 1) {
            // second half's state loads, front-batched
#pragma unroll
            for (int k = 0; k < 4; ++k) {
                int jj = q + ((k + 4) << 6);
                s_[k]  = g_sed[cbase + jj];
                w_[k]  = g_wat[cbase + jj];
                v_[k]  = g_vel[cbase + jj];
                rn_[k] = rrow[jj];
            }
        }

#pragma unroll
        for (int k = 0; k < 4; ++k) {
            int jj = q + ((half * 4 + k) << 6);

            float tcm = smc[jj];
            float tcf = tcm + 1.0f;

            float dx;
            if (interior_i) {
                dx = 0.5f * (smc[jj + PADW] - smc[jj - PADW]);
            } else {
                dx = 0.5f * (tcf * rowsc - tcf);
            }

            float dy;
            if (jj == 0)             dy = 0.5f * (tcf * 1.1f - tcf);
            else if (jj == Wd - 1)   dy = 0.5f * (tcf * 0.9f - tcf);
            else                     dy = 0.5f * (smc[jj + 1] - smc[jj - 1]);

            float rinv = rsqrtf(dx * dx + dy * dy + 1e-11f);
            float fdx = dx * rinv;
            float fdy = dy * rinv;

            // bilinear gather — entirely from SMEM (logical rows i0-2..i0+9 staged)
            float fx = (float)jj - fdx;
            float fy = fi - fdy;
            float x0 = floorf(fx), y0 = floorf(fy);
            float wx = fx - x0, wy = fy - y0;
            int ix = (int)x0;
            int iy = (int)y0;

            const float* g = sm + (iy - i0 + 2) * PADW + (ix + 4);
            float g00 = g[0];
            float g10 = g[1];
            float g01 = g[PADW];
            float g11 = g[PADW + 1];
            float nb = (1.0f - wy) * ((1.0f - wx) * g00 + wx * g10)
                     + wy          * ((1.0f - wx) * g01 + wx * g11) + 1.0f;

            float hd = tcf - nb;
            float nhd = (hd > pA.y) ? fmaxf(hd, pA.z) : 0.0f;

            float s = s_[k];
            float w = w_[k] + pA.x * rn_[k];

            float scap = nhd * pA.w * v_[k] * w;
            float first = fminf(fmaxf(-hd, 0.0f), s);
            float sdiff = s - scap;
            float third = (hd < 0.0f) ? 0.0f
                        : (fmaxf(sdiff * pB.y, 0.0f) - fmaxf(-sdiff * pB.x, 0.0f));
            float dep = fmaxf(-fmaxf(hd, 0.0f), first + third);

            float s2 = s - dep;
            float t2 = tcf + dep;

            // displace factor: r1+r2+r3 with column-boundary zeroing
            float ad = fabsf(fdy);
            float r2v = fmaxf(1.0f - ad, 0.0f);
            float fac = ad + r2v;
            if (jj == 0)        fac = fmaxf(-fdy, 0.0f) + r2v;  // t3 zeroed at col 0
            if (jj == Wd - 1)   fac = r2v + fmaxf(fdy, 0.0f);   // t1 zeroed at col W-1

            int cidx = cbase + jj;
            g_sed[cidx] = fac * s2;
            g_wat[cidx] = (fac * w) * pB.z;
            g_vel[cidx] = pB.w * hd;
            if (LAST) {
                outp[cidx] = fmaxf(1.0f + (1.0f - t2 * 2.0f), 0.0f) - 1.0f;
            } else {
                porow[jj] = t2 - 1.0f;
            }
        }
    }
}

extern "C" void kernel_launch(void* const* d_in, const int* in_sizes, int n_in,
                              void* d_out, int out_size) {
    const float* input     = (const float*)d_in[0];
    const float* rainall   = (const float*)d_in[1];
    // d_in[2] (random_gradient) provably unused: factor == relu(1e-10 - mag) == 0 in fp32.
    const float* rain_rate = (const float*)d_in[3];
    const float* evap      = (const float*)d_in[4];
    const float* minhd     = (const float*)d_in[5];
    const float* heps      = (const float*)d_in[6];
    const float* grav      = (const float*)d_in[7];
    const float* kc        = (const float*)d_in[8];
    const float* dis       = (const float*)d_in[9];
    const float* depr      = (const float*)d_in[10];
    float* out = (float*)d_out;

    float *pA, *pB;
    cudaGetSymbolAddress((void**)&pA, g_padA);
    cudaGetSymbolAddress((void**)&pB, g_padB);

    param_kernel<<<1, 1>>>(rain_rate, evap, minhd, heps, grav, kc, dis, depr);
    init_kernel<<<BATCH * PADH, PADW>>>(input);

    for (int it = 0; it < 10; ++it) {
        const float* pin = (it & 1) ? pB : pA;
        float* pout      = (it & 1) ? pA : pB;
        const float* rain = rainall + (size_t)it * NPIX;
        if (it == 9) {
            step_kernel<true><<<BATCH * (Wd / ROWS_PB), 512>>>(pin, pout, rain, out);
        } else {
            step_kernel<false><<<BATCH * (Wd / ROWS_PB), 512>>>(pin, pout, rain, out);
        }
    }
}

// round 9
// speedup vs baseline: 1.1728x; 1.1728x over previous
#include <cuda_runtime.h>
#include <cstdint>

#define Wd 512
#define BATCH 16
#define NPIX (Wd * Wd)
#define NTOT (BATCH * NPIX)
#define PADW 520
#define PADH 516
#define PADN (PADW * PADH)
#define INV_CELL 2.56f  /* 1 / (200/512) */
#define ROWS_PB 4
#define FILL_BYTES ((ROWS_PB + 4) * PADW * 4)

// Padded tm1 (= terrain - 1) buffers, zero borders.
// Logical (i,j) lives at pad[(i+2)*PADW + (j+4)].
__device__ __align__(16) float g_padA[BATCH * PADN];
__device__ __align__(16) float g_padB[BATCH * PADN];
__device__ __align__(16) float2 g_sw[NTOT];     // x=sed y=wat
__device__ __align__(16) float g_vel[NTOT];
__device__ float g_par[8];

__global__ void param_kernel(const float* rr, const float* ev, const float* mh,
                             const float* he, const float* gr, const float* kc,
                             const float* di, const float* de) {
    g_par[0] = fmaxf(*rr, 0.0f);            // relu(rain_rate)
    g_par[1] = *he;                         // height_epsilon
    g_par[2] = *mh;                         // min_height_delta
    g_par[3] = fmaxf(*kc, 0.0f) * INV_CELL; // relu(kc)/CELL_W
    g_par[4] = *di;                         // dissolving_rate
    g_par[5] = *de;                         // deposition_rate
    g_par[6] = 1.0f - fmaxf(*ev, 0.0f);     // 1 - relu(evap)
    g_par[7] = fmaxf(*gr, 0.0f) * INV_CELL; // relu(g)/CELL_W
}

__global__ void init_kernel(const float* __restrict__ in) {
    int row = blockIdx.x;            // 0 .. BATCH*PADH-1
    int b = row / PADH;
    int pi = row - b * PADH;
    int pj = threadIdx.x;            // 0 .. 519
    int pidx = b * PADN + pi * PADW + pj;
    if (pi >= 2 && pi < 2 + Wd && pj >= 4 && pj < 4 + Wd) {
        int i = pi - 2, j = pj - 4;
        int cidx = b * NPIX + i * Wd + j;
        float t0 = (1.0f - in[cidx]) * 0.5f;
        g_padA[pidx] = t0 - 1.0f;            // reference's tm1, exactly
        g_sw[cidx] = make_float2(0.0f, 0.0f);
        g_vel[cidx] = 0.0f;
    } else {
        // borders must be zero; interiors of B are written by step 0 before read
        g_padA[pidx] = 0.0f;
        g_padB[pidx] = 0.0f;
    }
}

__device__ __forceinline__ uint32_t smem_u32(const void* p) {
    uint32_t a;
    asm("{ .reg .u64 t; cvta.to.shared.u64 t, %1; cvt.u32.u64 %0, t; }"
        : "=r"(a) : "l"(p));
    return a;
}

template <bool LAST>
__global__ void __launch_bounds__(256)
step_kernel(const float* __restrict__ pin, float* __restrict__ pout,
            const float* __restrict__ rain, float* __restrict__ outp) {
    // padded rows i0..i0+7 (logical i0-2..i0+5)
    __shared__ __align__(16) float sm[(ROWS_PB + 4) * PADW];
    __shared__ __align__(8) unsigned long long mbar;

    int blk = blockIdx.x;
    int b = blk >> 7;            // batch (128 blocks per batch)
    int i0 = (blk & 127) << 2;   // first of 4 grid rows
    int t = threadIdx.x;
    int r = t >> 6;              // row within block (0..3)
    int q = t & 63;              // lane-position within row
    int i = i0 + r;

    uint32_t mb = smem_u32(&mbar);
    if (t == 0) {
        asm volatile("mbarrier.init.shared.b64 [%0], 1;" :: "r"(mb) : "memory");
    }
    __syncthreads();
    if (t == 0) {
        asm volatile("mbarrier.arrive.expect_tx.shared.b64 _, [%0], %1;"
                     :: "r"(mb), "r"(FILL_BYTES) : "memory");
        const float* src = pin + (size_t)b * PADN + (size_t)i0 * PADW;
        asm volatile(
            "cp.async.bulk.shared::cluster.global.mbarrier::complete_tx::bytes "
            "[%0], [%1], %2, [%3];"
            :: "r"(smem_u32(sm)), "l"(src), "r"(FILL_BYTES), "r"(mb) : "memory");
    }

    int cbase = b * NPIX + i * Wd;
    const float* rrow = rain + i * Wd;

    const float4* parv = reinterpret_cast<const float4*>(g_par);
    float4 pA = parv[0];  // x=rain_rate' y=heps z=minhd w=kc'
    float4 pB = parv[1];  // x=dis y=dep z=evap' w=grav'

    // ---- first half's state loads, front-batched to overlap the TMA fill ----
    float2 sw_[4];
    float v_[4], rn_[4];
#pragma unroll
    for (int k = 0; k < 4; ++k) {
        int jj = q + (k << 6);
        sw_[k] = g_sw[cbase + jj];
        v_[k]  = g_vel[cbase + jj];
        rn_[k] = rrow[jj];
    }

    // only warp 0 waits on the TMA mbarrier (HW-sleep); everyone else parks at the barrier
    if (t < 32) {
        uint32_t done = 0;
        while (!done) {
            asm volatile(
                "{ .reg .pred p; mbarrier.try_wait.parity.shared.b64 p, [%1], 0, 0x989680; "
                "selp.u32 %0, 1, 0, p; }"
                : "=r"(done) : "r"(mb) : "memory");
        }
    }
    __syncthreads();

    const float* smc = sm + (r + 2) * PADW + 4;   // this row's center, logical col 0
    bool interior_i = (i > 0) && (i < Wd - 1);
    float rowsc = (i == 0) ? 1.1f : 0.9f;
    float fi = (float)i;
    float* porow = pout + (size_t)b * PADN + (size_t)(i + 2) * PADW + 4;

#pragma unroll
    for (int half = 0; half < 2; ++half) {
        if (half == 1) {
            // second half's state loads, front-batched
#pragma unroll
            for (int k = 0; k < 4; ++k) {
                int jj = q + ((k + 4) << 6);
                sw_[k] = g_sw[cbase + jj];
                v_[k]  = g_vel[cbase + jj];
                rn_[k] = rrow[jj];
            }
        }

#pragma unroll
        for (int k = 0; k < 4; ++k) {
            int jj = q + ((half * 4 + k) << 6);

            float tcm = smc[jj];   // tm1-space terrain

            float dx;
            if (interior_i) {
                dx = 0.5f * (smc[jj + PADW] - smc[jj - PADW]);
            } else {
                float tcf = tcm + 1.0f;
                dx = 0.5f * (tcf * rowsc - tcf);
            }

            float dy;
            if (jj == 0) {
                float tcf = tcm + 1.0f;
                dy = 0.5f * (tcf * 1.1f - tcf);
            } else if (jj == Wd - 1) {
                float tcf = tcm + 1.0f;
                dy = 0.5f * (tcf * 0.9f - tcf);
            } else {
                dy = 0.5f * (smc[jj + 1] - smc[jj - 1]);
            }

            float rinv = rsqrtf(dx * dx + dy * dy + 1e-11f);
            float fdx = dx * rinv;
            float fdy = dy * rinv;

            // bilinear gather — entirely from SMEM (logical rows i0-2..i0+5 staged)
            float fx = (float)jj - fdx;
            float fy = fi - fdy;
            float x0 = floorf(fx), y0 = floorf(fy);
            float wx = fx - x0, wy = fy - y0;
            int ix = (int)x0;
            int iy = (int)y0;

            const float* g = sm + (iy - i0 + 2) * PADW + (ix + 4);
            float g00 = g[0];
            float g10 = g[1];
            float g01 = g[PADW];
            float g11 = g[PADW + 1];
            // nbm = neighbor - 1 (bilerp of tm1, zero-padded)
            float nbm = (1.0f - wy) * ((1.0f - wx) * g00 + wx * g10)
                      + wy          * ((1.0f - wx) * g01 + wx * g11);

            float hd = tcm - nbm;
            float nhd = (hd > pA.y) ? fmaxf(hd, pA.z) : 0.0f;

            float s = sw_[k].x;
            float w = sw_[k].y + pA.x * rn_[k];

            float scap = nhd * pA.w * v_[k] * w;
            float first = fminf(fmaxf(-hd, 0.0f), s);
            float sdiff = s - scap;
            float third = (hd < 0.0f) ? 0.0f
                        : (fmaxf(sdiff * pB.y, 0.0f) - fmaxf(-sdiff * pB.x, 0.0f));
            float dep = fmaxf(-fmaxf(hd, 0.0f), first + third);

            float s2 = s - dep;
            float t2m = tcm + dep;    // = new terrain - 1

            // displace factor: r1+r2+r3 with column-boundary zeroing
            float ad = fabsf(fdy);
            float r2v = fmaxf(1.0f - ad, 0.0f);
            float fac = ad + r2v;
            if (jj == 0)        fac = fmaxf(-fdy, 0.0f) + r2v;  // t3 zeroed at col 0
            if (jj == Wd - 1)   fac = r2v + fmaxf(fdy, 0.0f);   // t1 zeroed at col W-1

            int cidx = cbase + jj;
            g_sw[cidx] = make_float2(fac * s2, (fac * w) * pB.z);
            g_vel[cidx] = pB.w * hd;
            if (LAST) {
                // relu(2 - 2*t2) - 1 == relu(-2*t2m) - 1
                outp[cidx] = fmaxf(-2.0f * t2m, 0.0f) - 1.0f;
            } else {
                porow[jj] = t2m;
            }
        }
    }
}

extern "C" void kernel_launch(void* const* d_in, const int* in_sizes, int n_in,
                              void* d_out, int out_size) {
    const float* input     = (const float*)d_in[0];
    const float* rainall   = (const float*)d_in[1];
    // d_in[2] (random_gradient) provably unused: factor == relu(1e-10 - mag) == 0 in fp32.
    const float* rain_rate = (const float*)d_in[3];
    const float* evap      = (const float*)d_in[4];
    const float* minhd     = (const float*)d_in[5];
    const float* heps      = (const float*)d_in[6];
    const float* grav      = (const float*)d_in[7];
    const float* kc        = (const float*)d_in[8];
    const float* dis       = (const float*)d_in[9];
    const float* depr      = (const float*)d_in[10];
    float* out = (float*)d_out;

    float *pA, *pB;
    cudaGetSymbolAddress((void**)&pA, g_padA);
    cudaGetSymbolAddress((void**)&pB, g_padB);

    param_kernel<<<1, 1>>>(rain_rate, evap, minhd, heps, grav, kc, dis, depr);
    init_kernel<<<BATCH * PADH, PADW>>>(input);

    for (int it = 0; it < 10; ++it) {
        const float* pin = (it & 1) ? pB : pA;
        float* pout      = (it & 1) ? pA : pB;
        const float* rain = rainall + (size_t)it * NPIX;
        if (it == 9) {
            step_kernel<true><<<BATCH * 128, 256>>>(pin, pout, rain, out);
        } else {
            step_kernel<false><<<BATCH * 128, 256>>>(pin, pout, rain, out);
        }
    }
}